// round 1
// baseline (speedup 1.0000x reference)
#include <cuda_runtime.h>
#include <cuda_bf16.h>
#include <math.h>

// Problem constants
#define TT 512
#define BB 256
#define IN_DIM 256
#define H1 512
#define HH 256
#define OUT_DIM 18
#define MTOT (TT*BB)   // 131072

// -------------------- scratch (static device globals; no allocs) -----------
__device__ float d_buf1[(size_t)MTOT * 512]; // A1 (fc1a out) and later Q1 (fc2a out)
__device__ float d_A2 [(size_t)MTOT * 256];  // fc1b out
__device__ float d_GI [(size_t)MTOT * 768];  // gi = A2 @ W_ih^T + b_ih
__device__ float d_HALL[(size_t)MTOT * 256]; // h_t history
__device__ float d_H0 [BB * HH];             // zero initial state

// -------------------- generic fp32 GEMM: C = act(A[M,K] @ W[N,K]^T + b) ----
#define BM 128
#define BN 128
#define BKK 16

template<bool RELU>
__global__ void __launch_bounds__(256, 2) gemm_bias_act(
    const float* __restrict__ A, const float* __restrict__ W,
    const float* __restrict__ bias, float* __restrict__ C,
    int M, int N, int K)
{
    __shared__ float As[BKK][BM + 4];
    __shared__ float Ws[BKK][BN + 4];

    const int tid = threadIdx.x;
    const int m0 = blockIdx.y * BM;
    const int n0 = blockIdx.x * BN;
    const int tx = tid & 15;   // 16 cols of threads
    const int ty = tid >> 4;   // 16 rows of threads

    float acc[8][8];
    #pragma unroll
    for (int i = 0; i < 8; i++)
        #pragma unroll
        for (int j = 0; j < 8; j++) acc[i][j] = 0.f;

    for (int k0 = 0; k0 < K; k0 += BKK) {
        // load A tile [BM x BK] -> As[k][m] (transposed)
        #pragma unroll
        for (int i = 0; i < 2; i++) {
            int idx = tid + 256 * i;           // 0..511
            int r = idx >> 2;                  // 0..127
            int c4 = idx & 3;                  // 0..3
            float4 v = *(const float4*)&A[(size_t)(m0 + r) * K + k0 + c4 * 4];
            As[c4*4+0][r] = v.x; As[c4*4+1][r] = v.y;
            As[c4*4+2][r] = v.z; As[c4*4+3][r] = v.w;
        }
        // load W tile [BN x BK] -> Ws[k][n] (transposed)
        #pragma unroll
        for (int i = 0; i < 2; i++) {
            int idx = tid + 256 * i;
            int r = idx >> 2;
            int c4 = idx & 3;
            float4 v = *(const float4*)&W[(size_t)(n0 + r) * K + k0 + c4 * 4];
            Ws[c4*4+0][r] = v.x; Ws[c4*4+1][r] = v.y;
            Ws[c4*4+2][r] = v.z; Ws[c4*4+3][r] = v.w;
        }
        __syncthreads();

        #pragma unroll
        for (int kk = 0; kk < BKK; kk++) {
            float a[8], b[8];
            *(float4*)&a[0] = *(const float4*)&As[kk][ty * 8];
            *(float4*)&a[4] = *(const float4*)&As[kk][ty * 8 + 4];
            *(float4*)&b[0] = *(const float4*)&Ws[kk][tx * 8];
            *(float4*)&b[4] = *(const float4*)&Ws[kk][tx * 8 + 4];
            #pragma unroll
            for (int i = 0; i < 8; i++)
                #pragma unroll
                for (int j = 0; j < 8; j++)
                    acc[i][j] += a[i] * b[j];
        }
        __syncthreads();
    }

    // epilogue
    float bfrag[8];
    #pragma unroll
    for (int j = 0; j < 8; j++) bfrag[j] = bias[n0 + tx * 8 + j];

    #pragma unroll
    for (int i = 0; i < 8; i++) {
        size_t row = (size_t)(m0 + ty * 8 + i);
        #pragma unroll
        for (int j4 = 0; j4 < 2; j4++) {
            float4 v;
            float c0 = acc[i][j4*4+0] + bfrag[j4*4+0];
            float c1 = acc[i][j4*4+1] + bfrag[j4*4+1];
            float c2 = acc[i][j4*4+2] + bfrag[j4*4+2];
            float c3 = acc[i][j4*4+3] + bfrag[j4*4+3];
            if (RELU) {
                c0 = fmaxf(c0, 0.f); c1 = fmaxf(c1, 0.f);
                c2 = fmaxf(c2, 0.f); c3 = fmaxf(c3, 0.f);
            }
            v.x = c0; v.y = c1; v.z = c2; v.w = c3;
            *(float4*)&C[row * N + n0 + tx * 8 + j4 * 4] = v;
        }
    }
}

// -------------------- GRU step: gh GEMM + gates fused, one kernel/step -----
// grid: (B/32, 256/16) = (8,16); block 256 threads.
// Each CTA: b-tile of 32 rows, k-offset tile of 16; computes gh for the 3 gate
// rows {k, 256+k, 512+k} (48 W rows), then the full GRU gate update for its
// (b,k) outputs. Whh slice + transposed h tile live in smem.
__global__ void __launch_bounds__(256, 2) gru_step(
    const float* __restrict__ gi,      // [B,768] for this t
    const float* __restrict__ h_prev,  // [B,256]
    const float* __restrict__ Whh,     // [768,256]
    const float* __restrict__ bhh,     // [768]
    float* __restrict__ h_out)         // [B,256]
{
    extern __shared__ float sm[];
    float* Hs = sm;                 // [256][34]  h transposed: Hs[k][b]
    float* Wsm = sm + 256 * 34;     // [256][49]  W transposed: Wsm[k][j], j=gate*16+jr

    const int tid = threadIdx.x;
    const int b0 = blockIdx.x * 32;
    const int k0 = blockIdx.y * 16;

    // load h_prev tile [32 x 256] -> Hs[k][b]
    {
        int row = tid >> 3;   // 0..31
        int c = tid & 7;      // 0..7
        const float* hrow = &h_prev[(size_t)(b0 + row) * 256];
        #pragma unroll
        for (int i = 0; i < 8; i++) {
            int k4 = c + 8 * i;  // 0..63
            float4 v = *(const float4*)&hrow[k4 * 4];
            Hs[(k4*4+0)*34 + row] = v.x;
            Hs[(k4*4+1)*34 + row] = v.y;
            Hs[(k4*4+2)*34 + row] = v.z;
            Hs[(k4*4+3)*34 + row] = v.w;
        }
    }
    // load 48 Whh rows -> Wsm[k][j]
    {
        #pragma unroll
        for (int i = 0; i < 12; i++) {
            int idx = tid + 256 * i;   // 0..3071
            int jrow = idx >> 6;       // 0..47
            int k4 = idx & 63;         // 0..63
            int gate = jrow >> 4, jr = jrow & 15;
            float4 v = *(const float4*)&Whh[(size_t)(gate * 256 + k0 + jr) * 256 + k4 * 4];
            Wsm[(k4*4+0)*49 + jrow] = v.x;
            Wsm[(k4*4+1)*49 + jrow] = v.y;
            Wsm[(k4*4+2)*49 + jrow] = v.z;
            Wsm[(k4*4+3)*49 + jrow] = v.w;
        }
    }
    __syncthreads();

    const int q = tid & 15;   // k offset within tile
    const int p = tid >> 4;   // batch pair 0..15

    float ar0 = 0.f, ar1 = 0.f, az0 = 0.f, az1 = 0.f, an0 = 0.f, an1 = 0.f;
    #pragma unroll 8
    for (int kk = 0; kk < 256; kk++) {
        float2 h2 = *(const float2*)&Hs[kk * 34 + 2 * p];
        float wr = Wsm[kk * 49 + q];
        float wz = Wsm[kk * 49 + 16 + q];
        float wn = Wsm[kk * 49 + 32 + q];
        ar0 += h2.x * wr; ar1 += h2.y * wr;
        az0 += h2.x * wz; az1 += h2.y * wz;
        an0 += h2.x * wn; an1 += h2.y * wn;
    }

    const int kg = k0 + q;
    const float br = bhh[kg], bz = bhh[256 + kg], bn = bhh[512 + kg];

    #pragma unroll
    for (int e = 0; e < 2; e++) {
        int b = b0 + 2 * p + e;
        float hr = (e ? ar1 : ar0) + br;
        float hz = (e ? az1 : az0) + bz;
        float hn = (e ? an1 : an0) + bn;
        const float* gib = &gi[(size_t)b * 768];
        float ir = gib[kg];
        float iz = gib[256 + kg];
        float in_ = gib[512 + kg];
        float r = 1.f / (1.f + __expf(-(ir + hr)));
        float z = 1.f / (1.f + __expf(-(iz + hz)));
        float n = tanhf(in_ + r * hn);
        float hp = h_prev[(size_t)b * 256 + kg];
        h_out[(size_t)b * 256 + kg] = (1.f - z) * n + z * hp;
    }
}

// -------------------- fc2b head: out[M,18] = Q1[M,512] @ W[18,512]^T + b ---
__global__ void __launch_bounds__(256, 2) head_gemm(
    const float* __restrict__ A,   // [M,512]
    const float* __restrict__ Wb,  // [18,512]
    const float* __restrict__ bias,// [18]
    float* __restrict__ out, int M)
{
    __shared__ float Ws[18][512];  // 36 KB
    const int tid = threadIdx.x;
    #pragma unroll
    for (int i = 0; i < 9; i++) {
        int idx = tid + 256 * i;   // 0..2303 float4s
        ((float4*)&Ws[0][0])[idx] = ((const float4*)Wb)[idx];
    }
    __syncthreads();

    const size_t mbase = (size_t)blockIdx.x * 1024 + tid;

    float acc[4][18];
    #pragma unroll
    for (int i = 0; i < 4; i++)
        #pragma unroll
        for (int j = 0; j < 18; j++) acc[i][j] = 0.f;

    for (int k4 = 0; k4 < 128; k4++) {
        float4 a[4];
        #pragma unroll
        for (int i = 0; i < 4; i++)
            a[i] = *(const float4*)&A[(mbase + 256 * i) * 512 + k4 * 4];
        #pragma unroll
        for (int j = 0; j < 18; j++) {
            float4 w = *(const float4*)&Ws[j][k4 * 4];
            #pragma unroll
            for (int i = 0; i < 4; i++) {
                acc[i][j] += a[i].x * w.x;
                acc[i][j] += a[i].y * w.y;
                acc[i][j] += a[i].z * w.z;
                acc[i][j] += a[i].w * w.w;
            }
        }
    }

    #pragma unroll
    for (int i = 0; i < 4; i++) {
        size_t row = mbase + 256 * i;
        #pragma unroll
        for (int j = 0; j < 18; j++)
            out[row * 18 + j] = acc[i][j] + bias[j];
    }
}

__global__ void zero_k(float* p, int n) {
    int i = blockIdx.x * blockDim.x + threadIdx.x;
    if (i < n) p[i] = 0.f;
}

// -------------------- launch ------------------------------------------------
extern "C" void kernel_launch(void* const* d_in, const int* in_sizes, int n_in,
                              void* d_out, int out_size)
{
    (void)in_sizes; (void)n_in; (void)out_size;
    const float* x    = (const float*)d_in[0];
    const float* W1a  = (const float*)d_in[1];
    const float* b1a  = (const float*)d_in[2];
    const float* W1b  = (const float*)d_in[3];
    const float* b1b  = (const float*)d_in[4];
    const float* Wih  = (const float*)d_in[5];
    const float* bih  = (const float*)d_in[6];
    const float* Whh  = (const float*)d_in[7];
    const float* bhh  = (const float*)d_in[8];
    const float* W2a  = (const float*)d_in[9];
    const float* b2a  = (const float*)d_in[10];
    const float* W2b  = (const float*)d_in[11];
    const float* b2b  = (const float*)d_in[12];
    float* out = (float*)d_out;

    float *buf1, *A2, *GI, *HALL, *H0;
    cudaGetSymbolAddress((void**)&buf1, d_buf1);
    cudaGetSymbolAddress((void**)&A2,   d_A2);
    cudaGetSymbolAddress((void**)&GI,   d_GI);
    cudaGetSymbolAddress((void**)&HALL, d_HALL);
    cudaGetSymbolAddress((void**)&H0,   d_H0);

    const int gru_smem = (256 * 34 + 256 * 49) * 4;  // 84992 B
    cudaFuncSetAttribute(gru_step, cudaFuncAttributeMaxDynamicSharedMemorySize, gru_smem);

    const int M = MTOT;

    // fc1a: [M,256] -> [M,512], relu
    gemm_bias_act<true><<<dim3(512 / BN, M / BM), 256>>>(x, W1a, b1a, buf1, M, 512, 256);
    // fc1b: [M,512] -> [M,256], relu
    gemm_bias_act<true><<<dim3(256 / BN, M / BM), 256>>>(buf1, W1b, b1b, A2, M, 256, 512);
    // gi: [M,256] -> [M,768], no act
    gemm_bias_act<false><<<dim3(768 / BN, M / BM), 256>>>(A2, Wih, bih, GI, M, 768, 256);

    // zero initial hidden state
    zero_k<<<(BB * HH + 255) / 256, 256>>>(H0, BB * HH);

    // sequential GRU recurrence: one fused kernel per timestep
    for (int t = 0; t < TT; t++) {
        const float* hp = (t == 0) ? H0 : (HALL + (size_t)(t - 1) * BB * HH);
        gru_step<<<dim3(BB / 32, 256 / 16), 256, gru_smem>>>(
            GI + (size_t)t * BB * 768, hp, Whh, bhh,
            HALL + (size_t)t * BB * HH);
    }

    // fc2a: [M,256] -> [M,512], relu  (reuse buf1)
    gemm_bias_act<true><<<dim3(512 / BN, M / BM), 256>>>(HALL, W2a, b2a, buf1, M, 512, 256);
    // fc2b head: [M,512] -> [M,18]
    head_gemm<<<M / 1024, 256>>>(buf1, W2b, b2b, out, M);
}

// round 4
// speedup vs baseline: 1.3146x; 1.3146x over previous
#include <cuda_runtime.h>
#include <cuda_bf16.h>
#include <math.h>
#include <stdint.h>

// Problem constants
#define TT 512
#define BB 256
#define IN_DIM 256
#define H1 512
#define HH 256
#define OUT_DIM 18
#define MTOT (TT*BB)   // 131072

// -------------------- scratch (static device globals; no allocs) -----------
__device__ float d_buf1[(size_t)MTOT * 512]; // A1 (fc1a out) and later Q1 (fc2a out)
__device__ float d_A2 [(size_t)MTOT * 256];  // fc1b out
__device__ float d_GI [(size_t)MTOT * 768];  // gi = A2 @ W_ih^T + b_ih
__device__ float d_HALL[(size_t)MTOT * 256]; // h_t history
__device__ float d_H0 [BB * HH];             // zero initial state

// ==================== helpers ==============================================
__device__ __forceinline__ uint32_t smem_u32(const void* p) {
    uint32_t a;
    asm("{ .reg .u64 t; cvta.to.shared.u64 t, %1; cvt.u32.u64 %0, t; }"
        : "=r"(a) : "l"(p));
    return a;
}

__device__ __forceinline__ void ldsm4(uint32_t* r, uint32_t addr) {
    asm volatile("ldmatrix.sync.aligned.m8n8.x4.shared.b16 {%0,%1,%2,%3}, [%4];"
        : "=r"(r[0]), "=r"(r[1]), "=r"(r[2]), "=r"(r[3]) : "r"(addr));
}

__device__ __forceinline__ void mma16816(float* c, const uint32_t* a, const uint32_t* b) {
    asm volatile(
        "mma.sync.aligned.m16n8k16.row.col.f32.bf16.bf16.f32 "
        "{%0,%1,%2,%3}, {%4,%5,%6,%7}, {%8,%9}, {%0,%1,%2,%3};"
        : "+f"(c[0]), "+f"(c[1]), "+f"(c[2]), "+f"(c[3])
        : "r"(a[0]), "r"(a[1]), "r"(a[2]), "r"(a[3]), "r"(b[0]), "r"(b[1]));
}

__device__ __forceinline__ void split_bf16x4(float4 v, uint2& hv, uint2& lv) {
    __nv_bfloat16 h0 = __float2bfloat16(v.x);
    __nv_bfloat16 h1 = __float2bfloat16(v.y);
    __nv_bfloat16 h2 = __float2bfloat16(v.z);
    __nv_bfloat16 h3 = __float2bfloat16(v.w);
    __nv_bfloat16 l0 = __float2bfloat16(v.x - __bfloat162float(h0));
    __nv_bfloat16 l1 = __float2bfloat16(v.y - __bfloat162float(h1));
    __nv_bfloat16 l2 = __float2bfloat16(v.z - __bfloat162float(h2));
    __nv_bfloat16 l3 = __float2bfloat16(v.w - __bfloat162float(h3));
    hv.x = (uint32_t)__bfloat16_as_ushort(h0) | ((uint32_t)__bfloat16_as_ushort(h1) << 16);
    hv.y = (uint32_t)__bfloat16_as_ushort(h2) | ((uint32_t)__bfloat16_as_ushort(h3) << 16);
    lv.x = (uint32_t)__bfloat16_as_ushort(l0) | ((uint32_t)__bfloat16_as_ushort(l1) << 16);
    lv.y = (uint32_t)__bfloat16_as_ushort(l2) | ((uint32_t)__bfloat16_as_ushort(l3) << 16);
}

// ==================== mma.sync bf16-split GEMM ==============================
// C[M,N] = act(A[M,K] @ W[N,K]^T + b), fp32 in/out.
// fp32 -> (hi,lo) bf16 split at staging; D = Ah*Bh + Ah*Bl + Al*Bh.
// Tile: BM=128, BN=128, BK=32. 8 warps, warp tile 64x32 (4 m16 x 4 n8).
// smem rows padded to 80B (40 bf16) -> ldmatrix conflict-free.

#define ROWB 80          // bytes per smem row (32 bf16 data + pad)
#define SM_AHI 0
#define SM_ALO 10240
#define SM_BHI 20480
#define SM_BLO 30720
#define SM_GEMM_TOTAL 40960

template<bool RELU>
__global__ void __launch_bounds__(256, 2) gemm_mma(
    const float* __restrict__ A, const float* __restrict__ W,
    const float* __restrict__ bias, float* __restrict__ C,
    int M, int N, int K)
{
    __shared__ char sm[SM_GEMM_TOTAL];
    const uint32_t smb = smem_u32(sm);
    const int tid = threadIdx.x;
    const int lane = tid & 31;
    const int wid = tid >> 5;
    const int wm = wid & 1;        // 0..1  (M dir, 64 rows each)
    const int wn = wid >> 1;       // 0..3  (N dir, 32 cols each)
    const int m0 = blockIdx.y * 128;
    const int n0 = blockIdx.x * 128;

    float acc[4][4][4];
    #pragma unroll
    for (int i = 0; i < 4; i++)
        #pragma unroll
        for (int j = 0; j < 4; j++)
            #pragma unroll
            for (int e = 0; e < 4; e++) acc[i][j][e] = 0.f;

    // precomputed ldmatrix lane addressing
    const uint32_t a_row = (uint32_t)(lane & 15);
    const uint32_t a_kb  = (uint32_t)((lane >> 4) * 16);
    const uint32_t b_row = (uint32_t)(((lane >> 4) & 1) * 8 + (lane & 7));
    const uint32_t b_kb  = (uint32_t)(((lane >> 3) & 1) * 16);

    const int nchunks = K >> 5;   // BK=32
    for (int kc = 0; kc < nchunks; kc++) {
        const int kb = kc << 5;

        // ---- stage A chunk [128 x 32] fp32 -> bf16 hi/lo ----
        #pragma unroll
        for (int i = 0; i < 4; i++) {
            int idx = tid + 256 * i;    // 0..1023
            int r = idx >> 3;           // 0..127
            int c4 = idx & 7;           // float4 within row
            float4 v = *(const float4*)&A[(size_t)(m0 + r) * K + kb + c4 * 4];
            uint2 hv, lv; split_bf16x4(v, hv, lv);
            *(uint2*)(sm + SM_AHI + r * ROWB + c4 * 8) = hv;
            *(uint2*)(sm + SM_ALO + r * ROWB + c4 * 8) = lv;
        }
        // ---- stage B chunk [128 x 32] ----
        #pragma unroll
        for (int i = 0; i < 4; i++) {
            int idx = tid + 256 * i;
            int r = idx >> 3;
            int c4 = idx & 7;
            float4 v = *(const float4*)&W[(size_t)(n0 + r) * K + kb + c4 * 4];
            uint2 hv, lv; split_bf16x4(v, hv, lv);
            *(uint2*)(sm + SM_BHI + r * ROWB + c4 * 8) = hv;
            *(uint2*)(sm + SM_BLO + r * ROWB + c4 * 8) = lv;
        }
        __syncthreads();

        #pragma unroll
        for (int ks = 0; ks < 2; ks++) {
            const uint32_t koff = (uint32_t)(ks * 32);
            uint32_t afr[4][4];   // A fragments (hi first, reused for lo)
            uint32_t bhi[4][2], blo[4][2];

            // load A-hi fragments (4 m-tiles)
            #pragma unroll
            for (int mt = 0; mt < 4; mt++) {
                uint32_t addr = smb + SM_AHI +
                    (uint32_t)(wm * 64 + mt * 16 + a_row) * ROWB + koff + a_kb;
                ldsm4(afr[mt], addr);
            }
            // load B-hi fragments (4 n-tiles via 2 x4 loads)
            #pragma unroll
            for (int g = 0; g < 2; g++) {
                uint32_t r4[4];
                uint32_t addr = smb + SM_BHI +
                    (uint32_t)(wn * 32 + g * 16 + b_row) * ROWB + koff + b_kb;
                ldsm4(r4, addr);
                bhi[g*2  ][0] = r4[0]; bhi[g*2  ][1] = r4[1];
                bhi[g*2+1][0] = r4[2]; bhi[g*2+1][1] = r4[3];
            }
            // hi * hi
            #pragma unroll
            for (int mt = 0; mt < 4; mt++)
                #pragma unroll
                for (int nt = 0; nt < 4; nt++)
                    mma16816(acc[mt][nt], afr[mt], bhi[nt]);

            // load B-lo, hi * lo
            #pragma unroll
            for (int g = 0; g < 2; g++) {
                uint32_t r4[4];
                uint32_t addr = smb + SM_BLO +
                    (uint32_t)(wn * 32 + g * 16 + b_row) * ROWB + koff + b_kb;
                ldsm4(r4, addr);
                blo[g*2  ][0] = r4[0]; blo[g*2  ][1] = r4[1];
                blo[g*2+1][0] = r4[2]; blo[g*2+1][1] = r4[3];
            }
            #pragma unroll
            for (int mt = 0; mt < 4; mt++)
                #pragma unroll
                for (int nt = 0; nt < 4; nt++)
                    mma16816(acc[mt][nt], afr[mt], blo[nt]);

            // load A-lo into same regs, lo * hi
            #pragma unroll
            for (int mt = 0; mt < 4; mt++) {
                uint32_t addr = smb + SM_ALO +
                    (uint32_t)(wm * 64 + mt * 16 + a_row) * ROWB + koff + a_kb;
                ldsm4(afr[mt], addr);
            }
            #pragma unroll
            for (int mt = 0; mt < 4; mt++)
                #pragma unroll
                for (int nt = 0; nt < 4; nt++)
                    mma16816(acc[mt][nt], afr[mt], bhi[nt]);
        }
        __syncthreads();
    }

    // ---- epilogue: bias (+ relu), direct float2 stores ----
    const int r_in = lane >> 2;          // 0..7
    const int c_in = (lane & 3) * 2;     // 0,2,4,6
    #pragma unroll
    for (int mt = 0; mt < 4; mt++) {
        #pragma unroll
        for (int nt = 0; nt < 4; nt++) {
            int col = n0 + wn * 32 + nt * 8 + c_in;
            float b0 = bias[col], b1 = bias[col + 1];
            int row0 = m0 + wm * 64 + mt * 16 + r_in;
            float2 v0, v1;
            v0.x = acc[mt][nt][0] + b0; v0.y = acc[mt][nt][1] + b1;
            v1.x = acc[mt][nt][2] + b0; v1.y = acc[mt][nt][3] + b1;
            if (RELU) {
                v0.x = fmaxf(v0.x, 0.f); v0.y = fmaxf(v0.y, 0.f);
                v1.x = fmaxf(v1.x, 0.f); v1.y = fmaxf(v1.y, 0.f);
            }
            *(float2*)&C[(size_t)row0 * N + col] = v0;
            *(float2*)&C[(size_t)(row0 + 8) * N + col] = v1;
        }
    }
}

// -------------------- GRU step (unchanged, known-good) ----------------------
__global__ void __launch_bounds__(256, 2) gru_step(
    const float* __restrict__ gi,      // [B,768] for this t
    const float* __restrict__ h_prev,  // [B,256]
    const float* __restrict__ Whh,     // [768,256]
    const float* __restrict__ bhh,     // [768]
    float* __restrict__ h_out)         // [B,256]
{
    extern __shared__ float smf[];
    float* Hs = smf;                 // [256][34]
    float* Wsm = smf + 256 * 34;     // [256][49]

    const int tid = threadIdx.x;
    const int b0 = blockIdx.x * 32;
    const int k0 = blockIdx.y * 16;

    {
        int row = tid >> 3;
        int c = tid & 7;
        const float* hrow = &h_prev[(size_t)(b0 + row) * 256];
        #pragma unroll
        for (int i = 0; i < 8; i++) {
            int k4 = c + 8 * i;
            float4 v = *(const float4*)&hrow[k4 * 4];
            Hs[(k4*4+0)*34 + row] = v.x;
            Hs[(k4*4+1)*34 + row] = v.y;
            Hs[(k4*4+2)*34 + row] = v.z;
            Hs[(k4*4+3)*34 + row] = v.w;
        }
    }
    {
        #pragma unroll
        for (int i = 0; i < 12; i++) {
            int idx = tid + 256 * i;
            int jrow = idx >> 6;
            int k4 = idx & 63;
            int gate = jrow >> 4, jr = jrow & 15;
            float4 v = *(const float4*)&Whh[(size_t)(gate * 256 + k0 + jr) * 256 + k4 * 4];
            Wsm[(k4*4+0)*49 + jrow] = v.x;
            Wsm[(k4*4+1)*49 + jrow] = v.y;
            Wsm[(k4*4+2)*49 + jrow] = v.z;
            Wsm[(k4*4+3)*49 + jrow] = v.w;
        }
    }
    __syncthreads();

    const int q = tid & 15;
    const int p = tid >> 4;

    float ar0 = 0.f, ar1 = 0.f, az0 = 0.f, az1 = 0.f, an0 = 0.f, an1 = 0.f;
    #pragma unroll 8
    for (int kk = 0; kk < 256; kk++) {
        float2 h2 = *(const float2*)&Hs[kk * 34 + 2 * p];
        float wr = Wsm[kk * 49 + q];
        float wz = Wsm[kk * 49 + 16 + q];
        float wn = Wsm[kk * 49 + 32 + q];
        ar0 += h2.x * wr; ar1 += h2.y * wr;
        az0 += h2.x * wz; az1 += h2.y * wz;
        an0 += h2.x * wn; an1 += h2.y * wn;
    }

    const int kg = k0 + q;
    const float br = bhh[kg], bz = bhh[256 + kg], bn = bhh[512 + kg];

    #pragma unroll
    for (int e = 0; e < 2; e++) {
        int b = b0 + 2 * p + e;
        float hr = (e ? ar1 : ar0) + br;
        float hz = (e ? az1 : az0) + bz;
        float hn = (e ? an1 : an0) + bn;
        const float* gib = &gi[(size_t)b * 768];
        float ir = gib[kg];
        float iz = gib[256 + kg];
        float in_ = gib[512 + kg];
        float r = 1.f / (1.f + __expf(-(ir + hr)));
        float z = 1.f / (1.f + __expf(-(iz + hz)));
        float n = tanhf(in_ + r * hn);
        float hp = h_prev[(size_t)b * 256 + kg];
        h_out[(size_t)b * 256 + kg] = (1.f - z) * n + z * hp;
    }
}

// -------------------- fc2b head: out[M,18] = Q1[M,512] @ W[18,512]^T + b ---
__global__ void __launch_bounds__(256, 2) head_gemm(
    const float* __restrict__ A,
    const float* __restrict__ Wb,
    const float* __restrict__ bias,
    float* __restrict__ out, int M)
{
    __shared__ float Ws[18][512];
    const int tid = threadIdx.x;
    #pragma unroll
    for (int i = 0; i < 9; i++) {
        int idx = tid + 256 * i;
        ((float4*)&Ws[0][0])[idx] = ((const float4*)Wb)[idx];
    }
    __syncthreads();

    const size_t mbase = (size_t)blockIdx.x * 1024 + tid;

    float acc[4][18];
    #pragma unroll
    for (int i = 0; i < 4; i++)
        #pragma unroll
        for (int j = 0; j < 18; j++) acc[i][j] = 0.f;

    for (int k4 = 0; k4 < 128; k4++) {
        float4 a[4];
        #pragma unroll
        for (int i = 0; i < 4; i++)
            a[i] = *(const float4*)&A[(mbase + 256 * i) * 512 + k4 * 4];
        #pragma unroll
        for (int j = 0; j < 18; j++) {
            float4 w = *(const float4*)&Ws[j][k4 * 4];
            #pragma unroll
            for (int i = 0; i < 4; i++) {
                acc[i][j] += a[i].x * w.x;
                acc[i][j] += a[i].y * w.y;
                acc[i][j] += a[i].z * w.z;
                acc[i][j] += a[i].w * w.w;
            }
        }
    }

    #pragma unroll
    for (int i = 0; i < 4; i++) {
        size_t row = mbase + 256 * i;
        #pragma unroll
        for (int j = 0; j < 18; j++)
            out[row * 18 + j] = acc[i][j] + bias[j];
    }
}

__global__ void zero_k(float* p, int n) {
    int i = blockIdx.x * blockDim.x + threadIdx.x;
    if (i < n) p[i] = 0.f;
}

// -------------------- launch ------------------------------------------------
extern "C" void kernel_launch(void* const* d_in, const int* in_sizes, int n_in,
                              void* d_out, int out_size)
{
    (void)in_sizes; (void)n_in; (void)out_size;
    const float* x    = (const float*)d_in[0];
    const float* W1a  = (const float*)d_in[1];
    const float* b1a  = (const float*)d_in[2];
    const float* W1b  = (const float*)d_in[3];
    const float* b1b  = (const float*)d_in[4];
    const float* Wih  = (const float*)d_in[5];
    const float* bih  = (const float*)d_in[6];
    const float* Whh  = (const float*)d_in[7];
    const float* bhh  = (const float*)d_in[8];
    const float* W2a  = (const float*)d_in[9];
    const float* b2a  = (const float*)d_in[10];
    const float* W2b  = (const float*)d_in[11];
    const float* b2b  = (const float*)d_in[12];
    float* out = (float*)d_out;

    float *buf1, *A2, *GI, *HALL, *H0;
    cudaGetSymbolAddress((void**)&buf1, d_buf1);
    cudaGetSymbolAddress((void**)&A2,   d_A2);
    cudaGetSymbolAddress((void**)&GI,   d_GI);
    cudaGetSymbolAddress((void**)&HALL, d_HALL);
    cudaGetSymbolAddress((void**)&H0,   d_H0);

    const int gru_smem = (256 * 34 + 256 * 49) * 4;  // 84992 B
    cudaFuncSetAttribute(gru_step, cudaFuncAttributeMaxDynamicSharedMemorySize, gru_smem);

    const int M = MTOT;

    // fc1a: [M,256] -> [M,512], relu
    gemm_mma<true><<<dim3(512 / 128, M / 128), 256>>>(x, W1a, b1a, buf1, M, 512, 256);
    // fc1b: [M,512] -> [M,256], relu
    gemm_mma<true><<<dim3(256 / 128, M / 128), 256>>>(buf1, W1b, b1b, A2, M, 256, 512);
    // gi: [M,256] -> [M,768]
    gemm_mma<false><<<dim3(768 / 128, M / 128), 256>>>(A2, Wih, bih, GI, M, 768, 256);

    // zero initial hidden state
    zero_k<<<(BB * HH + 255) / 256, 256>>>(H0, BB * HH);

    // sequential GRU recurrence: one fused kernel per timestep
    for (int t = 0; t < TT; t++) {
        const float* hp = (t == 0) ? H0 : (HALL + (size_t)(t - 1) * BB * HH);
        gru_step<<<dim3(BB / 32, 256 / 16), 256, gru_smem>>>(
            GI + (size_t)t * BB * 768, hp, Whh, bhh,
            HALL + (size_t)t * BB * HH);
    }

    // fc2a: [M,256] -> [M,512], relu
    gemm_mma<true><<<dim3(512 / 128, M / 128), 256>>>(HALL, W2a, b2a, buf1, M, 512, 256);
    // fc2b head: [M,512] -> [M,18]
    head_gemm<<<M / 1024, 256>>>(buf1, W2b, b2b, out, M);
}

// round 5
// speedup vs baseline: 1.5151x; 1.1525x over previous
#include <cuda_runtime.h>
#include <cuda_bf16.h>
#include <math.h>
#include <stdint.h>

// Problem constants
#define TT 512
#define BB 256
#define IN_DIM 256
#define H1 512
#define HH 256
#define OUT_DIM 18
#define MTOT (TT*BB)   // 131072

// -------------------- scratch (static device globals; no allocs) -----------
__device__ float d_buf1[(size_t)MTOT * 512];     // fc2a out (fp32, for head)
__device__ float d_GI  [(size_t)MTOT * 768];     // gi fp32
__device__ float d_HALL[(size_t)MTOT * 256];     // h_t history fp32
__device__ float d_H0  [BB * HH];                // zero initial state

__device__ __nv_bfloat16 d_XHI[(size_t)MTOT * 256], d_XLO[(size_t)MTOT * 256];
__device__ __nv_bfloat16 d_A1HI[(size_t)MTOT * 512], d_A1LO[(size_t)MTOT * 512];
__device__ __nv_bfloat16 d_A2HI[(size_t)MTOT * 256], d_A2LO[(size_t)MTOT * 256];
__device__ __nv_bfloat16 d_HHI[(size_t)MTOT * 256], d_HLO[(size_t)MTOT * 256];
__device__ __nv_bfloat16 d_ZHI[BB * HH], d_ZLO[BB * HH];   // zero h split

__device__ __nv_bfloat16 d_W1AHI[512*256], d_W1ALO[512*256];
__device__ __nv_bfloat16 d_W1BHI[256*512], d_W1BLO[256*512];
__device__ __nv_bfloat16 d_WIHHI[768*256], d_WIHLO[768*256];
__device__ __nv_bfloat16 d_W2AHI[512*256], d_W2ALO[512*256];
__device__ __nv_bfloat16 d_WHHHI[768*256], d_WHHLO[768*256];

// ==================== helpers ==============================================
__device__ __forceinline__ uint32_t smem_u32(const void* p) {
    uint32_t a;
    asm("{ .reg .u64 t; cvta.to.shared.u64 t, %1; cvt.u32.u64 %0, t; }"
        : "=r"(a) : "l"(p));
    return a;
}

__device__ __forceinline__ void ldsm4(uint32_t* r, uint32_t addr) {
    asm volatile("ldmatrix.sync.aligned.m8n8.x4.shared.b16 {%0,%1,%2,%3}, [%4];"
        : "=r"(r[0]), "=r"(r[1]), "=r"(r[2]), "=r"(r[3]) : "r"(addr));
}
__device__ __forceinline__ void ldsm2(uint32_t* r, uint32_t addr) {
    asm volatile("ldmatrix.sync.aligned.m8n8.x2.shared.b16 {%0,%1}, [%2];"
        : "=r"(r[0]), "=r"(r[1]) : "r"(addr));
}

__device__ __forceinline__ void mma16816(float* c, const uint32_t* a, const uint32_t* b) {
    asm volatile(
        "mma.sync.aligned.m16n8k16.row.col.f32.bf16.bf16.f32 "
        "{%0,%1,%2,%3}, {%4,%5,%6,%7}, {%8,%9}, {%0,%1,%2,%3};"
        : "+f"(c[0]), "+f"(c[1]), "+f"(c[2]), "+f"(c[3])
        : "r"(a[0]), "r"(a[1]), "r"(a[2]), "r"(a[3]), "r"(b[0]), "r"(b[1]));
}

__device__ __forceinline__ void cp16(uint32_t dst, const void* src) {
    asm volatile("cp.async.cg.shared.global [%0], [%1], 16;"
        :: "r"(dst), "l"(src) : "memory");
}
#define CP_COMMIT() asm volatile("cp.async.commit_group;" ::: "memory")
#define CP_WAIT0()  asm volatile("cp.async.wait_group 0;" ::: "memory")
#define CP_WAIT1()  asm volatile("cp.async.wait_group 1;" ::: "memory")

__device__ __forceinline__ void split_bf16x4(float4 v, uint2& hv, uint2& lv) {
    __nv_bfloat16 h0 = __float2bfloat16(v.x);
    __nv_bfloat16 h1 = __float2bfloat16(v.y);
    __nv_bfloat16 h2 = __float2bfloat16(v.z);
    __nv_bfloat16 h3 = __float2bfloat16(v.w);
    __nv_bfloat16 l0 = __float2bfloat16(v.x - __bfloat162float(h0));
    __nv_bfloat16 l1 = __float2bfloat16(v.y - __bfloat162float(h1));
    __nv_bfloat16 l2 = __float2bfloat16(v.z - __bfloat162float(h2));
    __nv_bfloat16 l3 = __float2bfloat16(v.w - __bfloat162float(h3));
    hv.x = (uint32_t)__bfloat16_as_ushort(h0) | ((uint32_t)__bfloat16_as_ushort(h1) << 16);
    hv.y = (uint32_t)__bfloat16_as_ushort(h2) | ((uint32_t)__bfloat16_as_ushort(h3) << 16);
    lv.x = (uint32_t)__bfloat16_as_ushort(l0) | ((uint32_t)__bfloat16_as_ushort(l1) << 16);
    lv.y = (uint32_t)__bfloat16_as_ushort(l2) | ((uint32_t)__bfloat16_as_ushort(l3) << 16);
}

__device__ __forceinline__ uint32_t pack_hi2(float a, float b, uint32_t& lo) {
    __nv_bfloat16 ha = __float2bfloat16(a);
    __nv_bfloat16 hb = __float2bfloat16(b);
    __nv_bfloat16 la = __float2bfloat16(a - __bfloat162float(ha));
    __nv_bfloat16 lb = __float2bfloat16(b - __bfloat162float(hb));
    lo = (uint32_t)__bfloat16_as_ushort(la) | ((uint32_t)__bfloat16_as_ushort(lb) << 16);
    return (uint32_t)__bfloat16_as_ushort(ha) | ((uint32_t)__bfloat16_as_ushort(hb) << 16);
}

// -------------------- split / zero kernels ---------------------------------
__global__ void split_f32(const float4* __restrict__ in,
                          uint2* __restrict__ hi, uint2* __restrict__ lo, int n4) {
    int i = blockIdx.x * blockDim.x + threadIdx.x;
    if (i < n4) {
        uint2 h, l;
        split_bf16x4(in[i], h, l);
        hi[i] = h; lo[i] = l;
    }
}
__global__ void zero_f(float* p, int n) {
    int i = blockIdx.x * blockDim.x + threadIdx.x;
    if (i < n) p[i] = 0.f;
}
__global__ void zero_u32(uint32_t* p, int n) {
    int i = blockIdx.x * blockDim.x + threadIdx.x;
    if (i < n) p[i] = 0u;
}

// ==================== pipelined bf16-split GEMM =============================
// C = act(A @ W^T + b); A,W pre-split bf16 (hi,lo). BM=128,BN=128,BK=64.
// OUTM: 0 = fp32 C, 1 = bf16 hi/lo C.
#define GROW 144                 // smem row stride (128B data + 16 pad)
#define G_AHI 0
#define G_ALO 18432
#define G_BHI 36864
#define G_BLO 55296
#define G_STAGE 73728
#define G_SM_TOTAL (2*G_STAGE)   // 147456

template<bool RELU, int OUTM>
__global__ void __launch_bounds__(256, 1) gemm_bf(
    const __nv_bfloat16* __restrict__ Ahi, const __nv_bfloat16* __restrict__ Alo,
    const __nv_bfloat16* __restrict__ Bhi, const __nv_bfloat16* __restrict__ Blo,
    const float* __restrict__ bias,
    float* __restrict__ C, __nv_bfloat16* __restrict__ Chi, __nv_bfloat16* __restrict__ Clo,
    int M, int N, int K)
{
    extern __shared__ char sm[];
    const uint32_t smb = smem_u32(sm);
    const int tid = threadIdx.x;
    const int lane = tid & 31;
    const int wid = tid >> 5;
    const int wm = wid & 1;
    const int wn = wid >> 1;
    const int m0 = blockIdx.y * 128;
    const int n0 = blockIdx.x * 128;

    float acc[4][4][4];
    #pragma unroll
    for (int i = 0; i < 4; i++)
        #pragma unroll
        for (int j = 0; j < 4; j++)
            #pragma unroll
            for (int e = 0; e < 4; e++) acc[i][j][e] = 0.f;

    const uint32_t a_row = (uint32_t)(lane & 15);
    const uint32_t a_kb  = (uint32_t)((lane >> 4) * 16);
    const uint32_t b_row = (uint32_t)(((lane >> 4) & 1) * 8 + (lane & 7));
    const uint32_t b_kb  = (uint32_t)(((lane >> 3) & 1) * 16);

    const int nchunks = K >> 6;

    // chunk loader
    auto load_chunk = [&](int kc, int st) {
        const int kb = kc << 6;
        const uint32_t base = smb + (uint32_t)st * G_STAGE;
        #pragma unroll
        for (int j = 0; j < 4; j++) {
            int idx = tid + 256 * j;   // 0..1023
            int r = idx >> 3;          // 0..127
            int c = idx & 7;
            size_t aoff = (size_t)(m0 + r) * K + kb + c * 8;
            size_t boff = (size_t)(n0 + r) * K + kb + c * 8;
            uint32_t d = (uint32_t)(r * GROW + c * 16);
            cp16(base + G_AHI + d, Ahi + aoff);
            cp16(base + G_ALO + d, Alo + aoff);
            cp16(base + G_BHI + d, Bhi + boff);
            cp16(base + G_BLO + d, Blo + boff);
        }
        CP_COMMIT();
    };

    load_chunk(0, 0);

    for (int kc = 0; kc < nchunks; kc++) {
        const int st = kc & 1;
        if (kc + 1 < nchunks) { load_chunk(kc + 1, st ^ 1); CP_WAIT1(); }
        else                  { CP_WAIT0(); }
        __syncthreads();

        const uint32_t base = smb + (uint32_t)st * G_STAGE;
        #pragma unroll
        for (int ks = 0; ks < 4; ks++) {
            const uint32_t koff = (uint32_t)(ks * 32);
            uint32_t afr[4][4], bhi2[4][2], blo2[4][2];

            #pragma unroll
            for (int mt = 0; mt < 4; mt++)
                ldsm4(afr[mt], base + G_AHI + (uint32_t)(wm*64 + mt*16 + a_row)*GROW + koff + a_kb);
            #pragma unroll
            for (int g = 0; g < 2; g++) {
                uint32_t r4[4];
                ldsm4(r4, base + G_BHI + (uint32_t)(wn*32 + g*16 + b_row)*GROW + koff + b_kb);
                bhi2[g*2  ][0] = r4[0]; bhi2[g*2  ][1] = r4[1];
                bhi2[g*2+1][0] = r4[2]; bhi2[g*2+1][1] = r4[3];
            }
            #pragma unroll
            for (int mt = 0; mt < 4; mt++)
                #pragma unroll
                for (int nt = 0; nt < 4; nt++)
                    mma16816(acc[mt][nt], afr[mt], bhi2[nt]);

            #pragma unroll
            for (int g = 0; g < 2; g++) {
                uint32_t r4[4];
                ldsm4(r4, base + G_BLO + (uint32_t)(wn*32 + g*16 + b_row)*GROW + koff + b_kb);
                blo2[g*2  ][0] = r4[0]; blo2[g*2  ][1] = r4[1];
                blo2[g*2+1][0] = r4[2]; blo2[g*2+1][1] = r4[3];
            }
            #pragma unroll
            for (int mt = 0; mt < 4; mt++)
                #pragma unroll
                for (int nt = 0; nt < 4; nt++)
                    mma16816(acc[mt][nt], afr[mt], blo2[nt]);

            #pragma unroll
            for (int mt = 0; mt < 4; mt++)
                ldsm4(afr[mt], base + G_ALO + (uint32_t)(wm*64 + mt*16 + a_row)*GROW + koff + a_kb);
            #pragma unroll
            for (int mt = 0; mt < 4; mt++)
                #pragma unroll
                for (int nt = 0; nt < 4; nt++)
                    mma16816(acc[mt][nt], afr[mt], bhi2[nt]);
        }
        __syncthreads();
    }

    // ---- epilogue ----
    const int r_in = lane >> 2;
    const int c_in = (lane & 3) * 2;
    #pragma unroll
    for (int mt = 0; mt < 4; mt++) {
        #pragma unroll
        for (int nt = 0; nt < 4; nt++) {
            int col = n0 + wn * 32 + nt * 8 + c_in;
            float b0 = bias[col], b1 = bias[col + 1];
            int row0 = m0 + wm * 64 + mt * 16 + r_in;
            float v00 = acc[mt][nt][0] + b0, v01 = acc[mt][nt][1] + b1;
            float v10 = acc[mt][nt][2] + b0, v11 = acc[mt][nt][3] + b1;
            if (RELU) {
                v00 = fmaxf(v00, 0.f); v01 = fmaxf(v01, 0.f);
                v10 = fmaxf(v10, 0.f); v11 = fmaxf(v11, 0.f);
            }
            if (OUTM == 0) {
                float2 p0, p1;
                p0.x = v00; p0.y = v01; p1.x = v10; p1.y = v11;
                *(float2*)&C[(size_t)row0 * N + col] = p0;
                *(float2*)&C[(size_t)(row0 + 8) * N + col] = p1;
            } else {
                uint32_t lo0, lo1;
                uint32_t hi0 = pack_hi2(v00, v01, lo0);
                uint32_t hi1 = pack_hi2(v10, v11, lo1);
                *(uint32_t*)&Chi[(size_t)row0 * N + col] = hi0;
                *(uint32_t*)&Clo[(size_t)row0 * N + col] = lo0;
                *(uint32_t*)&Chi[(size_t)(row0 + 8) * N + col] = hi1;
                *(uint32_t*)&Clo[(size_t)(row0 + 8) * N + col] = lo1;
            }
        }
    }
}

// ==================== mma-based GRU step ====================================
// grid (8 btiles, 16 ktiles), 128 threads. CTA: 32b x 16k x 3 gates.
// gh tile M=32 x N=48 = h(32x256 split) @ Whh_slice(48x256 split)^T,
// then fused gates. Whh hi/lo pre-split; h hi/lo from previous step.
#define U_WHI 0
#define U_WLO 25344            // 48*528
#define U_HHI 50688
#define U_HLO 67584            // 32*528
#define U_GH  84480            // 32*49*4 = 6272
#define U_SM_TOTAL 90752
#define USTRIDE 528

__global__ void __launch_bounds__(128) gru_mma(
    const float* __restrict__ gi,            // [256,768] this t
    const float* __restrict__ hprev_f,       // [256,256]
    const __nv_bfloat16* __restrict__ hprev_hi,
    const __nv_bfloat16* __restrict__ hprev_lo,
    const __nv_bfloat16* __restrict__ whh_hi, // [768,256]
    const __nv_bfloat16* __restrict__ whh_lo,
    const float* __restrict__ bhh,           // [768]
    float* __restrict__ hout_f,
    __nv_bfloat16* __restrict__ hout_hi,
    __nv_bfloat16* __restrict__ hout_lo)
{
    extern __shared__ char sm[];
    const uint32_t smb = smem_u32(sm);
    float* GHs = (float*)(sm + U_GH);
    const int tid = threadIdx.x;
    const int lane = tid & 31;
    const int wid = tid >> 5;        // 0..3
    const int mh = wid & 1;          // M half (16 rows)
    const int nh = wid >> 1;         // N half (24 cols)
    const int b0 = blockIdx.x * 32;
    const int k0 = blockIdx.y * 16;

    // ---- stage W slice (48 rows) and h tile (32 rows), hi+lo, via cp.async
    for (int i = tid; i < 1536; i += 128) {          // W: 48 rows x 32 chunks
        int j = i >> 5;          // 0..47
        int c = i & 31;
        int g = j >> 4, jr = j & 15;
        size_t soff = (size_t)(g * 256 + k0 + jr) * 256 + c * 8;
        uint32_t d = (uint32_t)(j * USTRIDE + c * 16);
        cp16(smb + U_WHI + d, whh_hi + soff);
        cp16(smb + U_WLO + d, whh_lo + soff);
    }
    for (int i = tid; i < 1024; i += 128) {          // h: 32 rows x 32 chunks
        int r = i >> 5;
        int c = i & 31;
        size_t soff = (size_t)(b0 + r) * 256 + c * 8;
        uint32_t d = (uint32_t)(r * USTRIDE + c * 16);
        cp16(smb + U_HHI + d, hprev_hi + soff);
        cp16(smb + U_HLO + d, hprev_lo + soff);
    }
    CP_COMMIT();
    CP_WAIT0();
    __syncthreads();

    // ---- mma: M32 x N48 x K256, 3-term split
    float acc[3][4];
    #pragma unroll
    for (int i = 0; i < 3; i++)
        #pragma unroll
        for (int e = 0; e < 4; e++) acc[i][e] = 0.f;

    const uint32_t a_row = (uint32_t)(lane & 15);
    const uint32_t a_kb  = (uint32_t)((lane >> 4) * 16);
    const uint32_t b_row = (uint32_t)(((lane >> 4) & 1) * 8 + (lane & 7));
    const uint32_t b_kb  = (uint32_t)(((lane >> 3) & 1) * 16);
    const uint32_t b2_row = (uint32_t)(lane & 7);
    const uint32_t b2_kb  = (uint32_t)(((lane >> 3) & 1) * 16);

    const uint32_t aBaseHi = smb + U_HHI + (uint32_t)(mh * 16 + a_row) * USTRIDE + a_kb;
    const uint32_t aBaseLo = smb + U_HLO + (uint32_t)(mh * 16 + a_row) * USTRIDE + a_kb;
    const uint32_t bBaseHi4 = smb + U_WHI + (uint32_t)(nh * 24 + b_row) * USTRIDE + b_kb;
    const uint32_t bBaseLo4 = smb + U_WLO + (uint32_t)(nh * 24 + b_row) * USTRIDE + b_kb;
    const uint32_t bBaseHi2 = smb + U_WHI + (uint32_t)(nh * 24 + 16 + b2_row) * USTRIDE + b2_kb;
    const uint32_t bBaseLo2 = smb + U_WLO + (uint32_t)(nh * 24 + 16 + b2_row) * USTRIDE + b2_kb;

    #pragma unroll 4
    for (int ks = 0; ks < 16; ks++) {
        const uint32_t koff = (uint32_t)(ks * 32);
        uint32_t a[4], bh[3][2], bl[3][2], r4[4];

        ldsm4(a, aBaseHi + koff);
        ldsm4(r4, bBaseHi4 + koff);
        bh[0][0] = r4[0]; bh[0][1] = r4[1]; bh[1][0] = r4[2]; bh[1][1] = r4[3];
        ldsm2(bh[2], bBaseHi2 + koff);
        #pragma unroll
        for (int nt = 0; nt < 3; nt++) mma16816(acc[nt], a, bh[nt]);

        ldsm4(r4, bBaseLo4 + koff);
        bl[0][0] = r4[0]; bl[0][1] = r4[1]; bl[1][0] = r4[2]; bl[1][1] = r4[3];
        ldsm2(bl[2], bBaseLo2 + koff);
        #pragma unroll
        for (int nt = 0; nt < 3; nt++) mma16816(acc[nt], a, bl[nt]);

        ldsm4(a, aBaseLo + koff);
        #pragma unroll
        for (int nt = 0; nt < 3; nt++) mma16816(acc[nt], a, bh[nt]);
    }

    // ---- store gh to smem
    {
        const int r0 = lane >> 2;
        const int cc = (lane & 3) * 2;
        #pragma unroll
        for (int nt = 0; nt < 3; nt++) {
            int col = nh * 24 + nt * 8 + cc;
            GHs[(mh * 16 + r0) * 49 + col]     = acc[nt][0];
            GHs[(mh * 16 + r0) * 49 + col + 1] = acc[nt][1];
            GHs[(mh * 16 + r0 + 8) * 49 + col]     = acc[nt][2];
            GHs[(mh * 16 + r0 + 8) * 49 + col + 1] = acc[nt][3];
        }
    }
    __syncthreads();

    // ---- fused gates: 512 outputs, 4 per thread
    #pragma unroll
    for (int i = 0; i < 4; i++) {
        int idx = tid + 128 * i;
        int b = idx >> 4;          // 0..31
        int ko = idx & 15;         // 0..15
        int kg = k0 + ko;
        int bg = b0 + b;

        float hr = GHs[b * 49 + ko]      + bhh[kg];
        float hz = GHs[b * 49 + 16 + ko] + bhh[256 + kg];
        float hn = GHs[b * 49 + 32 + ko] + bhh[512 + kg];

        const float* gib = &gi[(size_t)bg * 768];
        float ir  = gib[kg];
        float iz  = gib[256 + kg];
        float in_ = gib[512 + kg];

        float r = 1.f / (1.f + __expf(-(ir + hr)));
        float z = 1.f / (1.f + __expf(-(iz + hz)));
        float n = tanhf(in_ + r * hn);
        float hp = hprev_f[(size_t)bg * 256 + kg];
        float hnew = (1.f - z) * n + z * hp;

        size_t off = (size_t)bg * 256 + kg;
        hout_f[off] = hnew;
        __nv_bfloat16 hh = __float2bfloat16(hnew);
        hout_hi[off] = hh;
        hout_lo[off] = __float2bfloat16(hnew - __bfloat162float(hh));
    }
}

// -------------------- fc2b head: out[M,18] = Q1[M,512] @ W[18,512]^T + b ---
__global__ void __launch_bounds__(256, 2) head_gemm(
    const float* __restrict__ A,
    const float* __restrict__ Wb,
    const float* __restrict__ bias,
    float* __restrict__ out, int M)
{
    __shared__ float Ws[18][512];
    const int tid = threadIdx.x;
    #pragma unroll
    for (int i = 0; i < 9; i++) {
        int idx = tid + 256 * i;
        ((float4*)&Ws[0][0])[idx] = ((const float4*)Wb)[idx];
    }
    __syncthreads();

    const size_t mbase = (size_t)blockIdx.x * 1024 + tid;

    float acc[4][18];
    #pragma unroll
    for (int i = 0; i < 4; i++)
        #pragma unroll
        for (int j = 0; j < 18; j++) acc[i][j] = 0.f;

    for (int k4 = 0; k4 < 128; k4++) {
        float4 a[4];
        #pragma unroll
        for (int i = 0; i < 4; i++)
            a[i] = *(const float4*)&A[(mbase + 256 * i) * 512 + k4 * 4];
        #pragma unroll
        for (int j = 0; j < 18; j++) {
            float4 w = *(const float4*)&Ws[j][k4 * 4];
            #pragma unroll
            for (int i = 0; i < 4; i++) {
                acc[i][j] += a[i].x * w.x;
                acc[i][j] += a[i].y * w.y;
                acc[i][j] += a[i].z * w.z;
                acc[i][j] += a[i].w * w.w;
            }
        }
    }

    #pragma unroll
    for (int i = 0; i < 4; i++) {
        size_t row = mbase + 256 * i;
        #pragma unroll
        for (int j = 0; j < 18; j++)
            out[row * 18 + j] = acc[i][j] + bias[j];
    }
}

// -------------------- launch ------------------------------------------------
extern "C" void kernel_launch(void* const* d_in, const int* in_sizes, int n_in,
                              void* d_out, int out_size)
{
    (void)in_sizes; (void)n_in; (void)out_size;
    const float* x    = (const float*)d_in[0];
    const float* W1a  = (const float*)d_in[1];
    const float* b1a  = (const float*)d_in[2];
    const float* W1b  = (const float*)d_in[3];
    const float* b1b  = (const float*)d_in[4];
    const float* Wih  = (const float*)d_in[5];
    const float* bih  = (const float*)d_in[6];
    const float* Whh  = (const float*)d_in[7];
    const float* bhh  = (const float*)d_in[8];
    const float* W2a  = (const float*)d_in[9];
    const float* b2a  = (const float*)d_in[10];
    const float* W2b  = (const float*)d_in[11];
    const float* b2b  = (const float*)d_in[12];
    float* out = (float*)d_out;

    float *buf1, *GI, *HALL, *H0;
    __nv_bfloat16 *XHI, *XLO, *A1HI, *A1LO, *A2HI, *A2LO, *HHI, *HLO, *ZHI, *ZLO;
    __nv_bfloat16 *W1AHI, *W1ALO, *W1BHI, *W1BLO, *WIHHI, *WIHLO, *W2AHI, *W2ALO, *WHHHI, *WHHLO;

    cudaGetSymbolAddress((void**)&buf1, d_buf1);
    cudaGetSymbolAddress((void**)&GI,   d_GI);
    cudaGetSymbolAddress((void**)&HALL, d_HALL);
    cudaGetSymbolAddress((void**)&H0,   d_H0);
    cudaGetSymbolAddress((void**)&XHI,  d_XHI);  cudaGetSymbolAddress((void**)&XLO,  d_XLO);
    cudaGetSymbolAddress((void**)&A1HI, d_A1HI); cudaGetSymbolAddress((void**)&A1LO, d_A1LO);
    cudaGetSymbolAddress((void**)&A2HI, d_A2HI); cudaGetSymbolAddress((void**)&A2LO, d_A2LO);
    cudaGetSymbolAddress((void**)&HHI,  d_HHI);  cudaGetSymbolAddress((void**)&HLO,  d_HLO);
    cudaGetSymbolAddress((void**)&ZHI,  d_ZHI);  cudaGetSymbolAddress((void**)&ZLO,  d_ZLO);
    cudaGetSymbolAddress((void**)&W1AHI, d_W1AHI); cudaGetSymbolAddress((void**)&W1ALO, d_W1ALO);
    cudaGetSymbolAddress((void**)&W1BHI, d_W1BHI); cudaGetSymbolAddress((void**)&W1BLO, d_W1BLO);
    cudaGetSymbolAddress((void**)&WIHHI, d_WIHHI); cudaGetSymbolAddress((void**)&WIHLO, d_WIHLO);
    cudaGetSymbolAddress((void**)&W2AHI, d_W2AHI); cudaGetSymbolAddress((void**)&W2ALO, d_W2ALO);
    cudaGetSymbolAddress((void**)&WHHHI, d_WHHHI); cudaGetSymbolAddress((void**)&WHHLO, d_WHHLO);

    cudaFuncSetAttribute(gemm_bf<true, 0>,  cudaFuncAttributeMaxDynamicSharedMemorySize, G_SM_TOTAL);
    cudaFuncSetAttribute(gemm_bf<true, 1>,  cudaFuncAttributeMaxDynamicSharedMemorySize, G_SM_TOTAL);
    cudaFuncSetAttribute(gemm_bf<false, 0>, cudaFuncAttributeMaxDynamicSharedMemorySize, G_SM_TOTAL);
    cudaFuncSetAttribute(gru_mma, cudaFuncAttributeMaxDynamicSharedMemorySize, U_SM_TOTAL);

    const int M = MTOT;

    // ---- pre-split inputs/weights to bf16 hi/lo ----
    split_f32<<<(M * 256 / 4 + 255) / 256, 256>>>((const float4*)x, (uint2*)XHI, (uint2*)XLO, M * 256 / 4);
    split_f32<<<128, 256>>>((const float4*)W1a, (uint2*)W1AHI, (uint2*)W1ALO, 512 * 256 / 4);
    split_f32<<<128, 256>>>((const float4*)W1b, (uint2*)W1BHI, (uint2*)W1BLO, 256 * 512 / 4);
    split_f32<<<192, 256>>>((const float4*)Wih, (uint2*)WIHHI, (uint2*)WIHLO, 768 * 256 / 4);
    split_f32<<<128, 256>>>((const float4*)W2a, (uint2*)W2AHI, (uint2*)W2ALO, 512 * 256 / 4);
    split_f32<<<192, 256>>>((const float4*)Whh, (uint2*)WHHHI, (uint2*)WHHLO, 768 * 256 / 4);

    zero_f<<<256, 256>>>(H0, BB * HH);
    zero_u32<<<128, 256>>>((uint32_t*)ZHI, BB * HH / 2);
    zero_u32<<<128, 256>>>((uint32_t*)ZLO, BB * HH / 2);

    // ---- batched GEMMs (tensor core, bf16-split) ----
    // fc1a: [M,256] -> [M,512] relu, split output
    gemm_bf<true, 1><<<dim3(4, M / 128), 256, G_SM_TOTAL>>>(
        XHI, XLO, W1AHI, W1ALO, b1a, nullptr, A1HI, A1LO, M, 512, 256);
    // fc1b: [M,512] -> [M,256] relu, split output
    gemm_bf<true, 1><<<dim3(2, M / 128), 256, G_SM_TOTAL>>>(
        A1HI, A1LO, W1BHI, W1BLO, b1b, nullptr, A2HI, A2LO, M, 256, 512);
    // gi: [M,256] -> [M,768] fp32 output
    gemm_bf<false, 0><<<dim3(6, M / 128), 256, G_SM_TOTAL>>>(
        A2HI, A2LO, WIHHI, WIHLO, bih, GI, nullptr, nullptr, M, 768, 256);

    // ---- sequential GRU (tensor core per step) ----
    for (int t = 0; t < TT; t++) {
        const float* hpf = (t == 0) ? H0 : (HALL + (size_t)(t - 1) * BB * HH);
        const __nv_bfloat16* hph = (t == 0) ? ZHI : (HHI + (size_t)(t - 1) * BB * HH);
        const __nv_bfloat16* hpl = (t == 0) ? ZLO : (HLO + (size_t)(t - 1) * BB * HH);
        gru_mma<<<dim3(8, 16), 128, U_SM_TOTAL>>>(
            GI + (size_t)t * BB * 768, hpf, hph, hpl,
            WHHHI, WHHLO, bhh,
            HALL + (size_t)t * BB * HH,
            HHI + (size_t)t * BB * HH,
            HLO + (size_t)t * BB * HH);
    }

    // fc2a: [M,256] -> [M,512] relu, fp32 out
    gemm_bf<true, 0><<<dim3(4, M / 128), 256, G_SM_TOTAL>>>(
        HHI, HLO, W2AHI, W2ALO, b2a, buf1, nullptr, nullptr, M, 512, 256);
    // fc2b head
    head_gemm<<<M / 1024, 256>>>(buf1, W2b, b2b, out, M);
}